// round 1
// baseline (speedup 1.0000x reference)
#include <cuda_runtime.h>
#include <cstdint>

// Problem constants
#define BATCH 64
#define TT    1000
#define NINP  64
#define HID   512
#define NACT  2

// Recurrence decomposition
#define CLUSTER_NCTA 8            // CTAs per cluster (W_hh split 8 ways by column)
#define NB           4            // batches per cluster
#define JPC          64           // HID / CLUSTER_NCTA columns per CTA
#define NCLUSTER     (BATCH / NB) // 16 clusters -> 128 CTAs

// d_out layout: [out | hn_last | rnn_out] in tuple order
#define HN_OFF  (BATCH * TT * NACT)          // 128000
#define RNN_OFF (HN_OFF + BATCH * HID)       // 160768

// ---------------------------------------------------------------------------
// Kernel A: inp_proj[b,t,:] = inp[b,t,:] @ W_ih  -> written into rnn region
// (consumed in-place by the recurrence kernel, which overwrites with h)
// ---------------------------------------------------------------------------
__global__ void __launch_bounds__(512, 1) k_inproj(
    const float* __restrict__ inp, const float* __restrict__ W_ih,
    float* __restrict__ rnn)
{
    __shared__ float xs[16][NINP];
    const int row0 = blockIdx.x * 16;
    for (int i = threadIdx.x; i < 16 * NINP; i += 512)
        xs[i >> 6][i & 63] = inp[(size_t)row0 * NINP + i];
    __syncthreads();

    const int j = threadIdx.x;  // output column 0..511
    float acc[16];
#pragma unroll
    for (int r = 0; r < 16; r++) acc[r] = 0.f;
#pragma unroll
    for (int k = 0; k < NINP; k++) {
        const float wv = W_ih[k * HID + j];
#pragma unroll
        for (int r = 0; r < 16; r++) acc[r] = fmaf(xs[r][k], wv, acc[r]);
    }
#pragma unroll
    for (int r = 0; r < 16; r++)
        rnn[(size_t)(row0 + r) * HID + j] = acc[r];
}

// ---------------------------------------------------------------------------
// Kernel B: persistent recurrence.
// Cluster of 8 CTAs handles NB=4 batches for all 1000 steps.
// Each CTA owns 64 output columns; its W_hh slice (512x64 fp32 = 128KB) lives
// in registers (128 floats/thread). h is double-buffered in SMEM; each step
// the CTA broadcasts its computed 64-column slice of h_next to all 8 cluster
// CTAs via st.shared::cluster, then barrier.cluster.
// ---------------------------------------------------------------------------
__global__ void __cluster_dims__(CLUSTER_NCTA, 1, 1) __launch_bounds__(256, 1)
k_rnn(const float* __restrict__ hn, const float* __restrict__ W_hh,
      float* __restrict__ rnn, float* __restrict__ hn_last)
{
    __shared__ float h_s[2][NB][HID];      // 16 KB, double buffered
    __shared__ float red[4][NB][JPC];      // 4 KB partial sums (k-group reduction)

    uint32_t rank;
    asm("mov.u32 %0, %%cluster_ctarank;" : "=r"(rank));
    const int cid    = blockIdx.x / CLUSTER_NCTA;
    const int j0     = (int)rank * JPC;
    const int b_base = cid * NB;

    const int tid = threadIdx.x;
    const int j   = tid & 63;   // local column within this CTA's 64
    const int kg  = tid >> 6;   // k-group 0..3 (each covers 128 k)

    // Resident W_hh slice: w[kk] = W_hh[kg*128+kk][j0+j]
    float w[128];
#pragma unroll
    for (int kk = 0; kk < 128; kk++)
        w[kk] = W_hh[(size_t)(kg * 128 + kk) * HID + j0 + j];

    // h0 into buffer 0 (full h for our 4 batches)
    for (int i = tid; i < NB * HID; i += 256)
        h_s[0][i >> 9][i & 511] = hn[(size_t)(b_base + (i >> 9)) * HID + (i & 511)];

    asm volatile("barrier.cluster.arrive.aligned;" ::: "memory");
    asm volatile("barrier.cluster.wait.aligned;" ::: "memory");

    // epilogue mapping: thread -> (batch b2, column j2)
    const int b2 = tid >> 6;
    const int j2 = tid & 63;

    // precompute DSMEM addresses of h_s[0][b2][j0+j2] in every cluster CTA
    const uint32_t la = (uint32_t)__cvta_generic_to_shared(&h_s[0][b2][j0 + j2]);
    uint32_t ra[CLUSTER_NCTA];
#pragma unroll
    for (int p = 0; p < CLUSTER_NCTA; p++)
        asm("mapa.shared::cluster.u32 %0, %1, %2;" : "=r"(ra[p]) : "r"(la), "r"(p));

    const float* __restrict__ hbase = &h_s[0][0][0];
    const int gb = b_base + b2;

#pragma unroll 1
    for (int t = 0; t < TT; t++) {
        // prefetch x_t (inp_proj) early; latency hidden by the FMA block below
        const size_t xoff = ((size_t)gb * TT + t) * HID + j0 + j2;
        const float xv = __ldg(&rnn[xoff]);

        const float* hc = hbase + (size_t)(t & 1) * (NB * HID);

        float acc[NB] = {0.f, 0.f, 0.f, 0.f};
#pragma unroll
        for (int kk = 0; kk < 128; kk += 4) {
#pragma unroll
            for (int b = 0; b < NB; b++) {
                const float4 hv4 = *reinterpret_cast<const float4*>(
                    &hc[b * HID + kg * 128 + kk]);
                acc[b] = fmaf(hv4.x, w[kk],     acc[b]);
                acc[b] = fmaf(hv4.y, w[kk + 1], acc[b]);
                acc[b] = fmaf(hv4.z, w[kk + 2], acc[b]);
                acc[b] = fmaf(hv4.w, w[kk + 3], acc[b]);
            }
        }
#pragma unroll
        for (int b = 0; b < NB; b++) red[kg][b][j] = acc[b];
        __syncthreads();

        // epilogue: reduce 4 k-groups, add x, sigmoid
        float v = red[0][b2][j2] + red[1][b2][j2] + red[2][b2][j2] + red[3][b2][j2];
        v += xv;
        const float hval = 1.f / (1.f + __expf(-v));

        rnn[xoff] = hval;                         // overwrite inp_proj with h
        if (t == TT - 1) hn_last[(size_t)gb * HID + j0 + j2] = hval;

        // broadcast our h slice into the NEXT buffer of every cluster CTA
        const uint32_t bufadd = (uint32_t)((1 - (t & 1)) * (NB * HID * 4));
#pragma unroll
        for (int p = 0; p < CLUSTER_NCTA; p++) {
            const uint32_t dst = ra[p] + bufadd;
            asm volatile("st.shared::cluster.f32 [%0], %1;"
                         :: "r"(dst), "f"(hval) : "memory");
        }

        // release our DSMEM stores / acquire peers'
        asm volatile("barrier.cluster.arrive.aligned;" ::: "memory");
        asm volatile("barrier.cluster.wait.aligned;" ::: "memory");
    }
}

// ---------------------------------------------------------------------------
// Kernel C: out = sigmoid(rnn_out @ W_fc + b_fc).  One warp per (b,t) row.
// HBM-bound (131 MB read).
// ---------------------------------------------------------------------------
__global__ void __launch_bounds__(256, 8) k_fc(
    const float* __restrict__ rnn, const float* __restrict__ W_fc,
    const float* __restrict__ b_fc, float* __restrict__ out)
{
    __shared__ float wfc[HID * NACT];
    for (int i = threadIdx.x; i < HID * NACT; i += 256) wfc[i] = W_fc[i];
    __syncthreads();

    const int warp = threadIdx.x >> 5, lane = threadIdx.x & 31;
    const size_t row = (size_t)blockIdx.x * 8 + warp;
    const float4* rp = reinterpret_cast<const float4*>(rnn + row * HID);

    float a0 = 0.f, a1 = 0.f;
#pragma unroll
    for (int i = 0; i < 4; i++) {
        const float4 vv = rp[lane + 32 * i];
        const int k = (lane + 32 * i) * 4;
        a0 = fmaf(vv.x, wfc[(k + 0) * 2 + 0], a0);
        a1 = fmaf(vv.x, wfc[(k + 0) * 2 + 1], a1);
        a0 = fmaf(vv.y, wfc[(k + 1) * 2 + 0], a0);
        a1 = fmaf(vv.y, wfc[(k + 1) * 2 + 1], a1);
        a0 = fmaf(vv.z, wfc[(k + 2) * 2 + 0], a0);
        a1 = fmaf(vv.z, wfc[(k + 2) * 2 + 1], a1);
        a0 = fmaf(vv.w, wfc[(k + 3) * 2 + 0], a0);
        a1 = fmaf(vv.w, wfc[(k + 3) * 2 + 1], a1);
    }
#pragma unroll
    for (int off = 16; off > 0; off >>= 1) {
        a0 += __shfl_xor_sync(0xffffffffu, a0, off);
        a1 += __shfl_xor_sync(0xffffffffu, a1, off);
    }
    if (lane == 0) {
        out[row * NACT + 0] = 1.f / (1.f + __expf(-(a0 + b_fc[0])));
        out[row * NACT + 1] = 1.f / (1.f + __expf(-(a1 + b_fc[1])));
    }
}

// ---------------------------------------------------------------------------
extern "C" void kernel_launch(void* const* d_in, const int* in_sizes, int n_in,
                              void* d_out, int out_size)
{
    const float* inp  = (const float*)d_in[0];
    const float* hn   = (const float*)d_in[1];
    const float* W_hh = (const float*)d_in[2];
    const float* W_ih = (const float*)d_in[3];
    const float* W_fc = (const float*)d_in[4];
    const float* b_fc = (const float*)d_in[5];

    float* out = (float*)d_out;
    float* hnl = out + HN_OFF;
    float* rnn = out + RNN_OFF;

    // 1) input projections for all timesteps (into rnn region, consumed in place)
    k_inproj<<<(BATCH * TT) / 16, 512>>>(inp, W_ih, rnn);

    // 2) persistent clustered recurrence (writes rnn_out and hn_last)
    k_rnn<<<NCLUSTER * CLUSTER_NCTA, 256>>>(hn, W_hh, rnn, hnl);

    // 3) output projection + sigmoid
    k_fc<<<(BATCH * TT) / 8, 256>>>(rnn, W_fc, b_fc, out);
}

// round 2
// speedup vs baseline: 1.2919x; 1.2919x over previous
#include <cuda_runtime.h>
#include <cstdint>

// Problem constants
#define BATCH 64
#define TT    1000
#define NINP  64
#define HID   512
#define NACT  2

// Recurrence decomposition
#define CNC  8                    // CTAs per cluster (W_hh split 8 ways by column)
#define NB   4                    // batches per cluster
#define JPC  64                   // HID / CNC columns per CTA
#define NCLUSTER (BATCH / NB)     // 16 clusters -> 128 CTAs

// d_out layout: [out | hn_last | rnn_out]
#define HN_OFF  (BATCH * TT * NACT)
#define RNN_OFF (HN_OFF + BATCH * HID)

typedef unsigned long long u64;
typedef unsigned int u32;

// ---- packed f32x2 helpers (Blackwell; ptxas never auto-fuses these) ----
__device__ __forceinline__ u64 pk(float lo, float hi) {
    u64 r; asm("mov.b64 %0, {%1, %2};" : "=l"(r) : "f"(lo), "f"(hi)); return r;
}
__device__ __forceinline__ void upk(u64 v, float& lo, float& hi) {
    asm("mov.b64 {%0, %1}, %2;" : "=f"(lo), "=f"(hi) : "l"(v));
}
__device__ __forceinline__ u64 f2fma(u64 a, u64 b, u64 c) {
    u64 d; asm("fma.rn.f32x2 %0, %1, %2, %3;" : "=l"(d) : "l"(a), "l"(b), "l"(c));
    return d;
}

// ---- mbarrier helpers ----
#define MBINIT(addr, cnt) \
    asm volatile("mbarrier.init.shared.b64 [%0], %1;" :: "r"(addr), "r"(cnt) : "memory")
#define MB_EXPECT(addr, tx) \
    asm volatile("mbarrier.arrive.expect_tx.shared.b64 _, [%0], %1;" :: "r"(addr), "r"(tx) : "memory")
#define MB_ARRIVE_REMOTE(addr) \
    asm volatile("mbarrier.arrive.shared::cluster.b64 _, [%0];" :: "r"(addr) : "memory")
#define WAITC(addr, ph) \
    asm volatile("{\n\t.reg .pred P;\n\tWL%=:\n\t" \
                 "mbarrier.try_wait.parity.acquire.cluster.shared::cta.b64 P, [%0], %1, 0x989680;\n\t" \
                 "@!P bra WL%=;\n\t}" :: "r"(addr), "r"(ph) : "memory")

// ---------------------------------------------------------------------------
// Kernel A: inp_proj[b,t,:] = inp[b,t,:] @ W_ih  (into rnn region, in-place)
// 32 rows per block; f32x2 over row pairs; LDS.128 over k pairs.
// ---------------------------------------------------------------------------
__global__ void __launch_bounds__(512, 1) k_inproj(
    const float* __restrict__ inp, const float* __restrict__ W_ih,
    float* __restrict__ rnn)
{
    __shared__ alignas(16) float2 xsp[16][NINP];   // [row_pair][k]
    const int row0 = blockIdx.x * 32;
    for (int i = threadIdx.x; i < 32 * NINP; i += 512) {
        const int r = i >> 6, k = i & 63;
        ((float*)&xsp[r >> 1][k])[r & 1] = inp[(size_t)(row0 + r) * NINP + k];
    }
    __syncthreads();

    const int j = threadIdx.x;
    u64 acc[16];
#pragma unroll
    for (int r2 = 0; r2 < 16; r2++) acc[r2] = 0ull;

#pragma unroll 8
    for (int k = 0; k < NINP; k += 2) {
        const float wa = W_ih[k * HID + j];
        const float wb = W_ih[(k + 1) * HID + j];
        const u64 w0 = pk(wa, wa), w1 = pk(wb, wb);
#pragma unroll
        for (int r2 = 0; r2 < 16; r2++) {
            const ulonglong2 hv = *reinterpret_cast<const ulonglong2*>(&xsp[r2][k]);
            acc[r2] = f2fma(hv.x, w0, acc[r2]);
            acc[r2] = f2fma(hv.y, w1, acc[r2]);
        }
    }
#pragma unroll
    for (int r2 = 0; r2 < 16; r2++) {
        float lo, hi; upk(acc[r2], lo, hi);
        rnn[(size_t)(row0 + 2 * r2) * HID + j]     = lo;
        rnn[(size_t)(row0 + 2 * r2 + 1) * HID + j] = hi;
    }
}

// ---------------------------------------------------------------------------
// Kernel B: persistent clustered recurrence (mbarrier + st.async protocol).
// ---------------------------------------------------------------------------
__global__ void __cluster_dims__(CNC, 1, 1) __launch_bounds__(256, 1)
k_rnn(const float* __restrict__ hn, const float* __restrict__ W_hh,
      float* __restrict__ rnn, float* __restrict__ hn_last)
{
    __shared__ alignas(16) float h_s[2][NB][HID];   // 16 KB double buffer
    __shared__ alignas(16) float red[4][NB][JPC];   // 4 KB k-group partials
    __shared__ alignas(8)  u64   mb[4];             // full0 full1 empty0 empty1

    u32 rank; asm("mov.u32 %0, %%cluster_ctarank;" : "=r"(rank));
    const int cid    = blockIdx.x / CNC;
    const int j0     = (int)rank * JPC;
    const int b_base = cid * NB;

    const int tid = threadIdx.x;
    const int j   = tid & 63;     // local column (also epilogue j2)
    const int kg  = tid >> 6;     // k-group 0..3 (also epilogue batch b2)
    const int col = j0 + j;
    const int gb  = b_base + kg;

    // W_hh slice: packed pairs over k. w2[k2] = (W[kbase+2k2][col], W[kbase+2k2+1][col])
    u64 w2[64];
#pragma unroll
    for (int k2 = 0; k2 < 64; k2++) {
        const int k = kg * 128 + 2 * k2;
        w2[k2] = pk(W_hh[(size_t)k * HID + col], W_hh[(size_t)(k + 1) * HID + col]);
    }

    // h0 -> buffer 0 (each CTA keeps a full local copy of its 4 batches)
    for (int i = tid; i < NB * HID; i += 256)
        h_s[0][i >> 9][i & 511] = hn[(size_t)(b_base + (i >> 9)) * HID + (i & 511)];

    const u32 mb_base = (u32)__cvta_generic_to_shared(&mb[0]);
    if (tid == 0) {
        MBINIT(mb_base + 0,  1);    // full0 (tx-based, 1 arrive = expect_tx poster)
        MBINIT(mb_base + 8,  1);    // full1
        MBINIT(mb_base + 16, CNC);  // empty0 (8 read-done arrivals)
        MBINIT(mb_base + 24, CNC);  // empty1
    }
    __syncthreads();
    asm volatile("barrier.cluster.arrive.aligned;\n\t"
                 "barrier.cluster.wait.aligned;" ::: "memory");

    // remote addresses: our h slot (buf0) and mbar block in every cluster CTA
    const u32 slot_l = (u32)__cvta_generic_to_shared(&h_s[0][kg][col]);
    u32 ra[CNC], rm[CNC];
#pragma unroll
    for (int p = 0; p < CNC; p++) {
        asm("mapa.shared::cluster.u32 %0, %1, %2;" : "=r"(ra[p]) : "r"(slot_l), "r"(p));
        asm("mapa.shared::cluster.u32 %0, %1, %2;" : "=r"(rm[p]) : "r"(mb_base), "r"(p));
    }

    const float* __restrict__ hs0 = &h_s[0][0][0];

#pragma unroll 1
    for (int t = 0; t < TT; t++) {
        const int cur = t & 1, nxt = cur ^ 1, m = t >> 1;
        const u32 wp = (u32)((cur ? m : (m + 1)) & 1);
        const size_t xoff = ((size_t)gb * TT + t) * HID + col;
        const float xv = __ldg(&rnn[xoff]);        // prefetch before waits

        if (t > 0) WAITC(mb_base + cur * 8, wp);   // full[cur]: h_t ready

        const float* hc = hs0 + cur * (NB * HID);
        const ulonglong2* hp0 = (const ulonglong2*)(hc + 0 * HID + kg * 128);
        const ulonglong2* hp1 = (const ulonglong2*)(hc + 1 * HID + kg * 128);
        const ulonglong2* hp2 = (const ulonglong2*)(hc + 2 * HID + kg * 128);
        const ulonglong2* hp3 = (const ulonglong2*)(hc + 3 * HID + kg * 128);

        u64 a0 = 0ull, a1 = 0ull, a2 = 0ull, a3 = 0ull;
#pragma unroll
        for (int q = 0; q < 32; q++) {
            const ulonglong2 v0 = hp0[q];
            a0 = f2fma(v0.x, w2[2 * q], a0); a0 = f2fma(v0.y, w2[2 * q + 1], a0);
            const ulonglong2 v1 = hp1[q];
            a1 = f2fma(v1.x, w2[2 * q], a1); a1 = f2fma(v1.y, w2[2 * q + 1], a1);
            const ulonglong2 v2 = hp2[q];
            a2 = f2fma(v2.x, w2[2 * q], a2); a2 = f2fma(v2.y, w2[2 * q + 1], a2);
            const ulonglong2 v3 = hp3[q];
            a3 = f2fma(v3.x, w2[2 * q], a3); a3 = f2fma(v3.y, w2[2 * q + 1], a3);
        }
        {
            float lo, hi;
            upk(a0, lo, hi); red[kg][0][j] = lo + hi;
            upk(a1, lo, hi); red[kg][1][j] = lo + hi;
            upk(a2, lo, hi); red[kg][2][j] = lo + hi;
            upk(a3, lo, hi); red[kg][3][j] = lo + hi;
        }
        __syncthreads();   // all reads of h_s[cur] and red[] writes complete

        const bool last = (t == TT - 1);
        if (tid == 0 && !last) {
            MB_EXPECT(mb_base + nxt * 8, NB * HID * 4);   // full[nxt]: expect 8192 B
#pragma unroll
            for (int p = 0; p < CNC; p++)                 // read-done on empty[cur]
                MB_ARRIVE_REMOTE(rm[p] + 16 + (u32)(cur * 8));
        }

        // epilogue: thread (b2=kg, j2=j)
        float v = red[0][kg][j] + red[1][kg][j] + red[2][kg][j] + red[3][kg][j] + xv;
        const float hval = 1.f / (1.f + __expf(-v));
        rnn[xoff] = hval;

        if (!last) {
            if (t > 0) WAITC(mb_base + 16 + nxt * 8, wp);  // empty[nxt]: safe to overwrite
            const float hnb = __shfl_down_sync(0xffffffffu, hval, 1);
            if ((j & 1) == 0) {
                const u64 pv = pk(hval, hnb);
                const u32 bo = (u32)(nxt * (NB * HID * 4));
#pragma unroll
                for (int p = 0; p < CNC; p++) {
                    asm volatile(
                        "st.async.shared::cluster.mbarrier::complete_tx::bytes.b64 [%0], %1, [%2];"
                        :: "r"(ra[p] + bo), "l"(pv), "r"(rm[p] + (u32)(nxt * 8)) : "memory");
                }
            }
        } else {
            hn_last[(size_t)gb * HID + col] = hval;
        }
    }
}

// ---------------------------------------------------------------------------
// Kernel C: out = sigmoid(rnn_out @ W_fc + b_fc). One warp per (b,t) row.
// ---------------------------------------------------------------------------
__global__ void __launch_bounds__(256, 8) k_fc(
    const float* __restrict__ rnn, const float* __restrict__ W_fc,
    const float* __restrict__ b_fc, float* __restrict__ out)
{
    __shared__ float wfc[HID * NACT];
    for (int i = threadIdx.x; i < HID * NACT; i += 256) wfc[i] = W_fc[i];
    __syncthreads();

    const int warp = threadIdx.x >> 5, lane = threadIdx.x & 31;
    const size_t row = (size_t)blockIdx.x * 8 + warp;
    const float4* rp = reinterpret_cast<const float4*>(rnn + row * HID);

    float a0 = 0.f, a1 = 0.f;
#pragma unroll
    for (int i = 0; i < 4; i++) {
        const float4 vv = rp[lane + 32 * i];
        const int k = (lane + 32 * i) * 4;
        a0 = fmaf(vv.x, wfc[(k + 0) * 2 + 0], a0);
        a1 = fmaf(vv.x, wfc[(k + 0) * 2 + 1], a1);
        a0 = fmaf(vv.y, wfc[(k + 1) * 2 + 0], a0);
        a1 = fmaf(vv.y, wfc[(k + 1) * 2 + 1], a1);
        a0 = fmaf(vv.z, wfc[(k + 2) * 2 + 0], a0);
        a1 = fmaf(vv.z, wfc[(k + 2) * 2 + 1], a1);
        a0 = fmaf(vv.w, wfc[(k + 3) * 2 + 0], a0);
        a1 = fmaf(vv.w, wfc[(k + 3) * 2 + 1], a1);
    }
#pragma unroll
    for (int off = 16; off > 0; off >>= 1) {
        a0 += __shfl_xor_sync(0xffffffffu, a0, off);
        a1 += __shfl_xor_sync(0xffffffffu, a1, off);
    }
    if (lane == 0) {
        out[row * NACT + 0] = 1.f / (1.f + __expf(-(a0 + b_fc[0])));
        out[row * NACT + 1] = 1.f / (1.f + __expf(-(a1 + b_fc[1])));
    }
}

// ---------------------------------------------------------------------------
extern "C" void kernel_launch(void* const* d_in, const int* in_sizes, int n_in,
                              void* d_out, int out_size)
{
    const float* inp  = (const float*)d_in[0];
    const float* hn   = (const float*)d_in[1];
    const float* W_hh = (const float*)d_in[2];
    const float* W_ih = (const float*)d_in[3];
    const float* W_fc = (const float*)d_in[4];
    const float* b_fc = (const float*)d_in[5];

    float* out = (float*)d_out;
    float* hnl = out + HN_OFF;
    float* rnn = out + RNN_OFF;

    k_inproj<<<(BATCH * TT) / 32, 512>>>(inp, W_ih, rnn);
    k_rnn<<<NCLUSTER * CNC, 256>>>(hn, W_hh, rnn, hnl);
    k_fc<<<(BATCH * TT) / 8, 256>>>(rnn, W_fc, b_fc, out);
}